// round 13
// baseline (speedup 1.0000x reference)
#include <cuda_runtime.h>
#include <cuda_fp16.h>
#include <math.h>

#define DIMC   256
#define HEADS  4
#define HEAD_DIM 64
#define KEY_DIM  32
#define HIDDEN 512
#define BATCH  2
#define NPIX   4096
#define HWDIM  64
#define EPSBN  1e-5f

typedef unsigned long long u64;
typedef unsigned int u32;

__device__ __forceinline__ float ex2(float x) {
    float y; asm("ex2.approx.ftz.f32 %0, %1;" : "=f"(y) : "f"(x));
    return y;
}
__device__ __forceinline__ u32 cvt_tf32(float x) {
    u32 u; asm("cvt.rna.tf32.f32 %0, %1;" : "=r"(u) : "f"(x));
    return u;
}
__device__ __forceinline__ u32 h2pack(float lo, float hi) {
    u32 d; asm("cvt.rn.f16x2.f32 %0, %1, %2;" : "=r"(d) : "f"(hi), "f"(lo));
    return d;
}
__device__ __forceinline__ void mma_f16(float c[4], const u32 a[4], u32 b0, u32 b1) {
    asm("mma.sync.aligned.m16n8k16.row.col.f32.f16.f16.f32 "
        "{%0,%1,%2,%3},{%4,%5,%6,%7},{%8,%9},{%0,%1,%2,%3};"
        : "+f"(c[0]), "+f"(c[1]), "+f"(c[2]), "+f"(c[3])
        : "r"(a[0]), "r"(a[1]), "r"(a[2]), "r"(a[3]), "r"(b0), "r"(b1));
}
__device__ __forceinline__ void mma_tf32(float c[4], const u32 a[4], const u32 b[2]) {
    asm("mma.sync.aligned.m16n8k8.row.col.f32.tf32.tf32.f32 "
        "{%0,%1,%2,%3},{%4,%5,%6,%7},{%8,%9},{%0,%1,%2,%3};"
        : "+f"(c[0]), "+f"(c[1]), "+f"(c[2]), "+f"(c[3])
        : "r"(a[0]), "r"(a[1]), "r"(a[2]), "r"(a[3]), "r"(b[0]), "r"(b[1]));
}
// 4x 8x8 f16 matrices, non-transposed (fragment rows along contiguous dim)
__device__ __forceinline__ void ldmx4(u32& r0, u32& r1, u32& r2, u32& r3, u32 addr) {
    asm volatile("ldmatrix.sync.aligned.m8n8.x4.shared.b16 {%0,%1,%2,%3}, [%4];"
        : "=r"(r0), "=r"(r1), "=r"(r2), "=r"(r3) : "r"(addr));
}
__device__ __forceinline__ void cp16(u32 dst, const void* src) {
    asm volatile("cp.async.ca.shared.global [%0], [%1], 16;" :: "r"(dst), "l"(src));
}
__device__ __forceinline__ void cp_commit() {
    asm volatile("cp.async.commit_group;" ::: "memory");
}
__device__ __forceinline__ void cp_wait0() {
    asm volatile("cp.async.wait_group 0;" ::: "memory");
}

// Scratch (allocation-free rule: __device__ globals)
__device__ float g_qkv[BATCH * HIDDEN * NPIX]; // 16 MB
__device__ float g_y  [BATCH * DIMC  * NPIX];  //  8 MB
__device__ __half g_q16[BATCH * HEADS * NPIX * KEY_DIM];
__device__ __half g_k16[BATCH * HEADS * NPIX * KEY_DIM];
__device__ __half g_v16[BATCH * HEADS * HEAD_DIM * NPIX];

// ---------------------------------------------------------------------------
// tf32 tensor-core GEMM + folded BN (unchanged from round 8).
// ---------------------------------------------------------------------------
#define GW_STR 36
#define GX_STR 72
#define GW_FLOATS (128 * GW_STR)
#define GX_FLOATS (32 * GX_STR)
#define OFF_W0 0
#define OFF_W1 GW_FLOATS
#define OFF_X0 (2 * GW_FLOATS)
#define OFF_X1 (2 * GW_FLOATS + GX_FLOATS)
#define GEMM_SMEM_BYTES ((2 * GW_FLOATS + 2 * GX_FLOATS) * 4)

__global__ __launch_bounds__(128) void gemm_mma_kernel(
    const float* __restrict__ X, const float* __restrict__ W,
    const float* __restrict__ gg, const float* __restrict__ bb,
    const float* __restrict__ mm, const float* __restrict__ vv,
    float* __restrict__ Out, int M, int K)
{
    extern __shared__ float gsm[];
    const int n0 = blockIdx.x * 64;
    const int m0 = blockIdx.y * 128;
    const int bz = blockIdx.z;
    const float* Xb = X + (size_t)bz * K * NPIX;
    float*       Ob = Out + (size_t)bz * M * NPIX;

    const int t    = threadIdx.x;
    const int w    = t >> 5;
    const int lane = t & 31;
    const int r    = lane >> 2;
    const int cq   = lane & 3;
    const u32 smb  = (u32)__cvta_generic_to_shared(gsm);

    float acc[2][8][4];
#pragma unroll
    for (int g = 0; g < 2; g++)
#pragma unroll
        for (int nt = 0; nt < 8; nt++)
#pragma unroll
            for (int k = 0; k < 4; k++) acc[g][nt][k] = 0.f;

#define STAGE_G(k0, buf)                                                        \
    do {                                                                        \
        u32 wd = smb + ((buf) ? OFF_W1 : OFF_W0) * 4;                           \
        u32 xd = smb + ((buf) ? OFF_X1 : OFF_X0) * 4;                           \
        _Pragma("unroll")                                                       \
        for (int c = 0; c < 8; c++) {                                           \
            int idx = t + c * 128;                                              \
            int m = idx >> 3, kc = idx & 7;                                     \
            cp16(wd + (m * GW_STR + kc * 4) * 4,                                \
                 &W[(size_t)(m0 + m) * K + (k0) + kc * 4]);                     \
        }                                                                       \
        _Pragma("unroll")                                                       \
        for (int c = 0; c < 4; c++) {                                           \
            int idx = t + c * 128;                                              \
            int kk = idx >> 4, n4 = (idx & 15) * 4;                             \
            cp16(xd + (kk * GX_STR + n4) * 4,                                   \
                 &Xb[(size_t)((k0) + kk) * NPIX + n0 + n4]);                    \
        }                                                                       \
        cp_commit();                                                            \
    } while (0)

    STAGE_G(0, 0);
    const int nchunks = K / 32;
    for (int c0 = 0; c0 < nchunks; c0++) {
        cp_wait0();
        __syncthreads();
        if (c0 < nchunks - 1) STAGE_G((c0 + 1) * 32, (c0 + 1) & 1);

        const float* Wt = gsm + ((c0 & 1) ? OFF_W1 : OFF_W0);
        const float* Xs = gsm + ((c0 & 1) ? OFF_X1 : OFF_X0);
#pragma unroll
        for (int ks = 0; ks < 4; ks++) {
            u32 a[2][4];
#pragma unroll
            for (int g = 0; g < 2; g++) {
                int mr = 64 * g + 16 * w + r;
                a[g][0] = cvt_tf32(Wt[(mr    ) * GW_STR + ks * 8 + cq    ]);
                a[g][1] = cvt_tf32(Wt[(mr + 8) * GW_STR + ks * 8 + cq    ]);
                a[g][2] = cvt_tf32(Wt[(mr    ) * GW_STR + ks * 8 + cq + 4]);
                a[g][3] = cvt_tf32(Wt[(mr + 8) * GW_STR + ks * 8 + cq + 4]);
            }
#pragma unroll
            for (int nt = 0; nt < 8; nt++) {
                u32 b[2];
                b[0] = cvt_tf32(Xs[(ks * 8 + cq    ) * GX_STR + nt * 8 + r]);
                b[1] = cvt_tf32(Xs[(ks * 8 + cq + 4) * GX_STR + nt * 8 + r]);
                mma_tf32(acc[0][nt], a[0], b);
                mma_tf32(acc[1][nt], a[1], b);
            }
        }
    }

#pragma unroll
    for (int g = 0; g < 2; g++) {
        int row0 = m0 + 64 * g + 16 * w + r;
        int row1 = row0 + 8;
        float sc0 = gg[row0] * rsqrtf(vv[row0] + EPSBN);
        float bi0 = bb[row0] - mm[row0] * sc0;
        float sc1 = gg[row1] * rsqrtf(vv[row1] + EPSBN);
        float bi1 = bb[row1] - mm[row1] * sc1;
#pragma unroll
        for (int nt = 0; nt < 8; nt++) {
            int col = n0 + nt * 8 + 2 * cq;
            *(float2*)&Ob[(size_t)row0 * NPIX + col] =
                make_float2(acc[g][nt][0] * sc0 + bi0, acc[g][nt][1] * sc0 + bi0);
            *(float2*)&Ob[(size_t)row1 * NPIX + col] =
                make_float2(acc[g][nt][2] * sc1 + bi1, acc[g][nt][3] * sc1 + bi1);
        }
    }
}

// ---------------------------------------------------------------------------
// Convert Q,K to half with transpose (unchanged).
// ---------------------------------------------------------------------------
__global__ __launch_bounds__(128) void qk_cvt_kernel()
{
    const float QSCALE = 0.17677669529663687f * 1.4426950408889634f;
    __shared__ float ts[32][132];
    const int n0 = blockIdx.x * 128;
    const int bh = blockIdx.y;
    const int b  = bh >> 2;
    const int h  = bh & 3;
    const int qk = blockIdx.z;
    const int t  = threadIdx.x;

    const float* src = g_qkv + ((size_t)(b * HIDDEN + h * 128 + (qk ? 32 : 0))) * NPIX + n0;
    __half* dst = (qk ? g_k16 : g_q16) + ((size_t)bh * NPIX + n0) * KEY_DIM;
    const float scale = qk ? 1.0f : QSCALE;

#pragma unroll
    for (int d = 0; d < 32; d++) ts[d][t] = src[(size_t)d * NPIX + t];
    __syncthreads();

    u32 out[16];
#pragma unroll
    for (int d = 0; d < 16; d++)
        out[d] = h2pack(ts[2 * d][t] * scale, ts[2 * d + 1][t] * scale);
#pragma unroll
    for (int q4 = 0; q4 < 4; q4++)
        *(uint4*)&dst[(size_t)t * 32 + q4 * 8] =
            make_uint4(out[q4 * 4], out[q4 * 4 + 1], out[q4 * 4 + 2], out[q4 * 4 + 3]);
}

__global__ __launch_bounds__(256) void v_cvt_kernel()
{
    int idx = blockIdx.x * 256 + threadIdx.x;
    if (idx >= BATCH * HEADS * HEAD_DIM * (NPIX / 4)) return;
    int n4   = (idx & 1023) * 4;
    int dv   = (idx >> 10) & 63;
    int bh   = idx >> 16;
    int b    = bh >> 2;
    int h    = bh & 3;
    const float* src = g_qkv + ((size_t)(b * HIDDEN + h * 128 + 64 + dv)) * NPIX + n4;
    __half* dst = g_v16 + ((size_t)bh * HEAD_DIM + dv) * NPIX + n4;
    float4 v = *(const float4*)src;
    *(uint2*)dst = make_uint2(h2pack(v.x, v.y), h2pack(v.z, v.w));
}

// ---------------------------------------------------------------------------
// Flash attention, fp16 mma + ldmatrix B-fragments, single pass over 4096 keys.
// 128 threads (4 warps); warp owns 32 queries (two 16-row tiles sharing K/V).
// Grid = (NPIX/128, BATCH*HEADS).
// ---------------------------------------------------------------------------
#define RK 40
#define RV 72
#define KS_H (64 * RK)
#define VS_H (64 * RV)
#define AKS0 0
#define AKS1 KS_H
#define AVS0 (2 * KS_H)
#define AVS1 (2 * KS_H + VS_H)

__global__ __launch_bounds__(128) void attn_mma_kernel()
{
    __shared__ __align__(16) __half smh[2 * KS_H + 2 * VS_H];  // 28672 B
    const int bh   = blockIdx.y;
    const int i0   = blockIdx.x * 128;
    const int t    = threadIdx.x;
    const int w    = t >> 5;
    const int lane = t & 31;
    const int r    = lane >> 2;
    const int cq   = lane & 3;
    const int m4   = lane >> 3;      // matrix index 0..3 within ldmatrix.x4
    const int li   = lane & 7;       // row within matrix

    const __half* qb = g_q16 + (size_t)bh * NPIX * KEY_DIM;
    const __half* kb = g_k16 + (size_t)bh * NPIX * KEY_DIM;
    const __half* vb = g_v16 + (size_t)bh * HEAD_DIM * NPIX;
    const u32 smb = (u32)__cvta_generic_to_shared(smh);

    // lane-dependent byte offsets for ldmatrix row addresses
    // row = (2*ntp + (m4>>1))*8 + li ; col base = 8*(m4&1)
    const u32 laneK = (u32)((((m4 >> 1) * 8 + li) * RK + (m4 & 1) * 8) * 2);
    const u32 laneV = (u32)((((m4 >> 1) * 8 + li) * RV + (m4 & 1) * 8) * 2);

    u32 qa[2][2][4];
#pragma unroll
    for (int rt = 0; rt < 2; rt++) {
        int row0 = i0 + 32 * w + 16 * rt + r;
#pragma unroll
        for (int ks = 0; ks < 2; ks++) {
            qa[rt][ks][0] = *(const u32*)&qb[(size_t)row0 * 32       + 16 * ks + 2 * cq];
            qa[rt][ks][1] = *(const u32*)&qb[(size_t)(row0 + 8) * 32 + 16 * ks + 2 * cq];
            qa[rt][ks][2] = *(const u32*)&qb[(size_t)row0 * 32       + 16 * ks + 8 + 2 * cq];
            qa[rt][ks][3] = *(const u32*)&qb[(size_t)(row0 + 8) * 32 + 16 * ks + 8 + 2 * cq];
        }
    }

    float o[2][8][4];
#pragma unroll
    for (int rt = 0; rt < 2; rt++)
#pragma unroll
        for (int nt = 0; nt < 8; nt++)
#pragma unroll
            for (int k = 0; k < 4; k++) o[rt][nt][k] = 0.f;
    float mx[2][2] = {{-1e30f, -1e30f}, {-1e30f, -1e30f}};
    float ll[2][2] = {{0.f, 0.f}, {0.f, 0.f}};

#define STAGE_A(kbase_idx, buf)                                                  \
    do {                                                                         \
        u32 kd = smb + ((buf) ? AKS1 : AKS0) * 2;                                \
        u32 vd = smb + ((buf) ? AVS1 : AVS0) * 2;                                \
        _Pragma("unroll")                                                        \
        for (int c = 0; c < 2; c++) {                                            \
            int idx = t + c * 128;                                               \
            int j = idx >> 2, seg = idx & 3;                                     \
            cp16(kd + (j * RK + seg * 8) * 2,                                    \
                 &kb[(size_t)((kbase_idx) + j) * 32 + seg * 8]);                 \
        }                                                                        \
        _Pragma("unroll")                                                        \
        for (int c = 0; c < 4; c++) {                                            \
            int idx = t + c * 128;                                               \
            int dv = idx >> 3, seg = idx & 7;                                    \
            cp16(vd + (dv * RV + seg * 8) * 2,                                   \
                 &vb[(size_t)dv * NPIX + (kbase_idx) + seg * 8]);                \
        }                                                                        \
        cp_commit();                                                             \
    } while (0)

    STAGE_A(0, 0);

    for (int tt = 0; tt < 64; tt++) {
        cp_wait0();
        __syncthreads();
        if (tt < 63) STAGE_A((tt + 1) * 64, (tt + 1) & 1);

        const u32 kBuf = smb + ((tt & 1) ? AKS1 : AKS0) * 2 + laneK;
        const u32 vBuf = smb + ((tt & 1) ? AVS1 : AVS0) * 2 + laneV;

        // ---- S = Q * K^T (K fragments shared across both row-tiles) ----
        float s[2][8][4];
#pragma unroll
        for (int rt = 0; rt < 2; rt++)
#pragma unroll
            for (int nt = 0; nt < 8; nt++)
#pragma unroll
                for (int k = 0; k < 4; k++) s[rt][nt][k] = 0.f;
#pragma unroll
        for (int ks = 0; ks < 2; ks++) {
#pragma unroll
            for (int ntp = 0; ntp < 4; ntp++) {
                u32 b00, b01, b10, b11;
                ldmx4(b00, b01, b10, b11,
                      kBuf + (u32)((ntp * 16 * RK + ks * 16) * 2));
                mma_f16(s[0][2 * ntp    ], qa[0][ks], b00, b01);
                mma_f16(s[1][2 * ntp    ], qa[1][ks], b00, b01);
                mma_f16(s[0][2 * ntp + 1], qa[0][ks], b10, b11);
                mma_f16(s[1][2 * ntp + 1], qa[1][ks], b10, b11);
            }
        }

        // ---- online softmax + pack P per row-tile ----
        u32 pa[2][4][4];
#pragma unroll
        for (int rt = 0; rt < 2; rt++) {
            float mx0 = mx[rt][0], mx1 = mx[rt][1];
#pragma unroll
            for (int nt = 0; nt < 8; nt++) {
                mx0 = fmaxf(mx0, fmaxf(s[rt][nt][0], s[rt][nt][1]));
                mx1 = fmaxf(mx1, fmaxf(s[rt][nt][2], s[rt][nt][3]));
            }
            mx0 = fmaxf(mx0, __shfl_xor_sync(0xffffffffu, mx0, 1));
            mx0 = fmaxf(mx0, __shfl_xor_sync(0xffffffffu, mx0, 2));
            mx1 = fmaxf(mx1, __shfl_xor_sync(0xffffffffu, mx1, 1));
            mx1 = fmaxf(mx1, __shfl_xor_sync(0xffffffffu, mx1, 2));
            float corr0 = ex2(mx[rt][0] - mx0);
            float corr1 = ex2(mx[rt][1] - mx1);
            mx[rt][0] = mx0; mx[rt][1] = mx1;

            float ps0 = 0.f, ps1 = 0.f;
#pragma unroll
            for (int nt = 0; nt < 8; nt++) {
                s[rt][nt][0] = ex2(s[rt][nt][0] - mx0);
                s[rt][nt][1] = ex2(s[rt][nt][1] - mx0);
                s[rt][nt][2] = ex2(s[rt][nt][2] - mx1);
                s[rt][nt][3] = ex2(s[rt][nt][3] - mx1);
                ps0 += s[rt][nt][0] + s[rt][nt][1];
                ps1 += s[rt][nt][2] + s[rt][nt][3];
            }
            ps0 += __shfl_xor_sync(0xffffffffu, ps0, 1);
            ps0 += __shfl_xor_sync(0xffffffffu, ps0, 2);
            ps1 += __shfl_xor_sync(0xffffffffu, ps1, 1);
            ps1 += __shfl_xor_sync(0xffffffffu, ps1, 2);
            ll[rt][0] = ll[rt][0] * corr0 + ps0;
            ll[rt][1] = ll[rt][1] * corr1 + ps1;

#pragma unroll
            for (int nt = 0; nt < 8; nt++) {
                o[rt][nt][0] *= corr0; o[rt][nt][1] *= corr0;
                o[rt][nt][2] *= corr1; o[rt][nt][3] *= corr1;
            }
#pragma unroll
            for (int ks2 = 0; ks2 < 4; ks2++) {
                pa[rt][ks2][0] = h2pack(s[rt][2 * ks2    ][0], s[rt][2 * ks2    ][1]);
                pa[rt][ks2][1] = h2pack(s[rt][2 * ks2    ][2], s[rt][2 * ks2    ][3]);
                pa[rt][ks2][2] = h2pack(s[rt][2 * ks2 + 1][0], s[rt][2 * ks2 + 1][1]);
                pa[rt][ks2][3] = h2pack(s[rt][2 * ks2 + 1][2], s[rt][2 * ks2 + 1][3]);
            }
        }

        // ---- O += P * V (V fragments via ldmatrix, shared across row-tiles) ----
#pragma unroll
        for (int ks2 = 0; ks2 < 4; ks2++) {
#pragma unroll
            for (int ntp = 0; ntp < 4; ntp++) {
                u32 b00, b01, b10, b11;
                ldmx4(b00, b01, b10, b11,
                      vBuf + (u32)((ntp * 16 * RV + ks2 * 16) * 2));
                mma_f16(o[0][2 * ntp    ], pa[0][ks2], b00, b01);
                mma_f16(o[1][2 * ntp    ], pa[1][ks2], b00, b01);
                mma_f16(o[0][2 * ntp + 1], pa[0][ks2], b10, b11);
                mma_f16(o[1][2 * ntp + 1], pa[1][ks2], b10, b11);
            }
        }
    }

    // ---- epilogue: normalize, store g_y [dv][n] ----
    const int b  = bh >> 2;
    const int h  = bh & 3;
    float* ybase = g_y + ((size_t)b * DIMC + h * 64) * NPIX;
#pragma unroll
    for (int rt = 0; rt < 2; rt++) {
        float inv0 = 1.f / ll[rt][0];
        float inv1 = 1.f / ll[rt][1];
        int row0 = i0 + 32 * w + 16 * rt + r;
        int row1 = row0 + 8;
#pragma unroll
        for (int nt = 0; nt < 8; nt++) {
            int dv0 = nt * 8 + 2 * cq;
            ybase[(size_t)(dv0    ) * NPIX + row0] = o[rt][nt][0] * inv0;
            ybase[(size_t)(dv0 + 1) * NPIX + row0] = o[rt][nt][1] * inv0;
            ybase[(size_t)(dv0    ) * NPIX + row1] = o[rt][nt][2] * inv1;
            ybase[(size_t)(dv0 + 1) * NPIX + row1] = o[rt][nt][3] * inv1;
        }
    }
}

// ---------------------------------------------------------------------------
// Depthwise 3x3 conv + BN, added into g_y (4-wide strips).
// ---------------------------------------------------------------------------
__global__ __launch_bounds__(256) void pe_add_kernel(
    const float* __restrict__ pw, const float* __restrict__ pg,
    const float* __restrict__ pb, const float* __restrict__ pm,
    const float* __restrict__ pv)
{
    int idx = blockIdx.x * 256 + threadIdx.x;
    if (idx >= BATCH * DIMC * (NPIX / 4)) return;
    int n4 = (idx & 1023) * 4;
    int c  = (idx >> 10) & 255;
    int b  = idx >> 18;
    int yy = n4 >> 6, xx = n4 & 63;

    int vrow = (c >> 6) * 128 + 64 + (c & 63);
    const float* vimg = g_qkv + ((size_t)b * HIDDEN + vrow) * NPIX;

    float a0 = 0.f, a1 = 0.f, a2 = 0.f, a3 = 0.f;
#pragma unroll
    for (int ky = 0; ky < 3; ky++) {
        int y2 = yy + ky - 1;
        if (y2 < 0 || y2 >= HWDIM) continue;
        const float* row = vimg + y2 * HWDIM;
        float lm1 = (xx > 0)  ? row[xx - 1] : 0.f;
        float4 lc = *(const float4*)&row[xx];
        float l4  = (xx < 60) ? row[xx + 4] : 0.f;
        float w0 = pw[c * 9 + ky * 3 + 0];
        float w1 = pw[c * 9 + ky * 3 + 1];
        float w2 = pw[c * 9 + ky * 3 + 2];
        a0 += w0 * lm1  + w1 * lc.x + w2 * lc.y;
        a1 += w0 * lc.x + w1 * lc.y + w2 * lc.z;
        a2 += w0 * lc.y + w1 * lc.z + w2 * lc.w;
        a3 += w0 * lc.z + w1 * lc.w + w2 * l4;
    }
    float sc = pg[c] * rsqrtf(pv[c] + EPSBN);
    float bi = pb[c] - pm[c] * sc;
    float* yp = &g_y[((size_t)b * DIMC + c) * NPIX + n4];
    float4 y = *(float4*)yp;
    y.x += a0 * sc + bi;
    y.y += a1 * sc + bi;
    y.z += a2 * sc + bi;
    y.w += a3 * sc + bi;
    *(float4*)yp = y;
}

// ---------------------------------------------------------------------------
extern "C" void kernel_launch(void* const* d_in, const int* in_sizes, int n_in,
                              void* d_out, int out_size)
{
    const float* x      = (const float*)d_in[0];
    const float* qkv_w  = (const float*)d_in[1];
    const float* qkv_g  = (const float*)d_in[2];
    const float* qkv_b  = (const float*)d_in[3];
    const float* qkv_m  = (const float*)d_in[4];
    const float* qkv_v  = (const float*)d_in[5];
    const float* proj_w = (const float*)d_in[6];
    const float* proj_g = (const float*)d_in[7];
    const float* proj_b = (const float*)d_in[8];
    const float* proj_m = (const float*)d_in[9];
    const float* proj_v = (const float*)d_in[10];
    const float* pe_w   = (const float*)d_in[11];
    const float* pe_g   = (const float*)d_in[12];
    const float* pe_b   = (const float*)d_in[13];
    const float* pe_m   = (const float*)d_in[14];
    const float* pe_v   = (const float*)d_in[15];
    float* out = (float*)d_out;

    static float* qkv_buf = nullptr;
    static float* y_buf   = nullptr;
    if (!qkv_buf) {
        cudaGetSymbolAddress((void**)&qkv_buf, g_qkv);
        cudaGetSymbolAddress((void**)&y_buf,   g_y);
        cudaFuncSetAttribute(gemm_mma_kernel,
                             cudaFuncAttributeMaxDynamicSharedMemorySize,
                             GEMM_SMEM_BYTES);
    }

    // 1) QKV 1x1 conv + BN
    {
        dim3 grid(NPIX / 64, HIDDEN / 128, BATCH);
        gemm_mma_kernel<<<grid, 128, GEMM_SMEM_BYTES>>>(
            x, qkv_w, qkv_g, qkv_b, qkv_m, qkv_v, qkv_buf, HIDDEN, DIMC);
    }
    // 2) Convert Q/K (transpose) and V to half
    {
        dim3 gridqk(NPIX / 128, BATCH * HEADS, 2);
        qk_cvt_kernel<<<gridqk, 128>>>();
        int vtot = BATCH * HEADS * HEAD_DIM * (NPIX / 4);
        v_cvt_kernel<<<(vtot + 255) / 256, 256>>>();
    }
    // 3) Attention (fp16 mma + ldmatrix, single pass)
    {
        dim3 grid(NPIX / 128, BATCH * HEADS);
        attn_mma_kernel<<<grid, 128>>>();
    }
    // 4) PE depthwise conv + BN, add into y
    {
        int total = BATCH * DIMC * (NPIX / 4);
        pe_add_kernel<<<(total + 255) / 256, 256>>>(pe_w, pe_g, pe_b, pe_m, pe_v);
    }
    // 5) proj 1x1 conv + BN -> out
    {
        dim3 grid(NPIX / 64, DIMC / 128, BATCH);
        gemm_mma_kernel<<<grid, 128, GEMM_SMEM_BYTES>>>(
            y_buf, proj_w, proj_g, proj_b, proj_m, proj_v, out, DIMC, DIMC);
    }
}

// round 15
// speedup vs baseline: 1.4472x; 1.4472x over previous
#include <cuda_runtime.h>
#include <cuda_fp16.h>
#include <math.h>

#define DIMC   256
#define HEADS  4
#define HEAD_DIM 64
#define KEY_DIM  32
#define HIDDEN 512
#define BATCH  2
#define NPIX   4096
#define HWDIM  64
#define EPSBN  1e-5f

typedef unsigned long long u64;
typedef unsigned int u32;

__device__ __forceinline__ float ex2(float x) {
    float y; asm("ex2.approx.ftz.f32 %0, %1;" : "=f"(y) : "f"(x));
    return y;
}
__device__ __forceinline__ u32 cvt_tf32(float x) {
    u32 u; asm("cvt.rna.tf32.f32 %0, %1;" : "=r"(u) : "f"(x));
    return u;
}
__device__ __forceinline__ u32 h2pack(float lo, float hi) {
    u32 d; asm("cvt.rn.f16x2.f32 %0, %1, %2;" : "=r"(d) : "f"(hi), "f"(lo));
    return d;
}
__device__ __forceinline__ void mma_f16(float c[4], const u32 a[4], u32 b0, u32 b1) {
    asm("mma.sync.aligned.m16n8k16.row.col.f32.f16.f16.f32 "
        "{%0,%1,%2,%3},{%4,%5,%6,%7},{%8,%9},{%0,%1,%2,%3};"
        : "+f"(c[0]), "+f"(c[1]), "+f"(c[2]), "+f"(c[3])
        : "r"(a[0]), "r"(a[1]), "r"(a[2]), "r"(a[3]), "r"(b0), "r"(b1));
}
__device__ __forceinline__ void mma_tf32(float c[4], const u32 a[4], const u32 b[2]) {
    asm("mma.sync.aligned.m16n8k8.row.col.f32.tf32.tf32.f32 "
        "{%0,%1,%2,%3},{%4,%5,%6,%7},{%8,%9},{%0,%1,%2,%3};"
        : "+f"(c[0]), "+f"(c[1]), "+f"(c[2]), "+f"(c[3])
        : "r"(a[0]), "r"(a[1]), "r"(a[2]), "r"(a[3]), "r"(b[0]), "r"(b[1]));
}
__device__ __forceinline__ void cp16(u32 dst, const void* src) {
    asm volatile("cp.async.ca.shared.global [%0], [%1], 16;" :: "r"(dst), "l"(src));
}
__device__ __forceinline__ void cp_commit() {
    asm volatile("cp.async.commit_group;" ::: "memory");
}
__device__ __forceinline__ void cp_wait0() {
    asm volatile("cp.async.wait_group 0;" ::: "memory");
}

// Scratch (allocation-free rule: __device__ globals)
__device__ float g_qkv[BATCH * HIDDEN * NPIX]; // 16 MB
__device__ float g_y  [BATCH * DIMC  * NPIX];  //  8 MB
__device__ __half g_q16[BATCH * HEADS * NPIX * KEY_DIM];
__device__ __half g_k16[BATCH * HEADS * NPIX * KEY_DIM];
__device__ __half g_v16[BATCH * HEADS * HEAD_DIM * NPIX];

// ---------------------------------------------------------------------------
// tf32 tensor-core GEMM + folded BN. When write_v != 0 (QKV pass), the g==1
// half of each 128-row block is exactly the V channels of one head; emit
// fp16 copies to g_v16 directly from registers (coalesced u32 stores).
// ---------------------------------------------------------------------------
#define GW_STR 36
#define GX_STR 72
#define GW_FLOATS (128 * GW_STR)
#define GX_FLOATS (32 * GX_STR)
#define OFF_W0 0
#define OFF_W1 GW_FLOATS
#define OFF_X0 (2 * GW_FLOATS)
#define OFF_X1 (2 * GW_FLOATS + GX_FLOATS)
#define GEMM_SMEM_BYTES ((2 * GW_FLOATS + 2 * GX_FLOATS) * 4)

__global__ __launch_bounds__(128) void gemm_mma_kernel(
    const float* __restrict__ X, const float* __restrict__ W,
    const float* __restrict__ gg, const float* __restrict__ bb,
    const float* __restrict__ mm, const float* __restrict__ vv,
    float* __restrict__ Out, int M, int K, int write_v)
{
    extern __shared__ float gsm[];
    const int n0 = blockIdx.x * 64;
    const int m0 = blockIdx.y * 128;
    const int bz = blockIdx.z;
    const float* Xb = X + (size_t)bz * K * NPIX;
    float*       Ob = Out + (size_t)bz * M * NPIX;

    const int t    = threadIdx.x;
    const int w    = t >> 5;
    const int lane = t & 31;
    const int r    = lane >> 2;
    const int cq   = lane & 3;
    const u32 smb  = (u32)__cvta_generic_to_shared(gsm);

    float acc[2][8][4];
#pragma unroll
    for (int g = 0; g < 2; g++)
#pragma unroll
        for (int nt = 0; nt < 8; nt++)
#pragma unroll
            for (int k = 0; k < 4; k++) acc[g][nt][k] = 0.f;

#define STAGE_G(k0, buf)                                                        \
    do {                                                                        \
        u32 wd = smb + ((buf) ? OFF_W1 : OFF_W0) * 4;                           \
        u32 xd = smb + ((buf) ? OFF_X1 : OFF_X0) * 4;                           \
        _Pragma("unroll")                                                       \
        for (int c = 0; c < 8; c++) {                                           \
            int idx = t + c * 128;                                              \
            int m = idx >> 3, kc = idx & 7;                                     \
            cp16(wd + (m * GW_STR + kc * 4) * 4,                                \
                 &W[(size_t)(m0 + m) * K + (k0) + kc * 4]);                     \
        }                                                                       \
        _Pragma("unroll")                                                       \
        for (int c = 0; c < 4; c++) {                                           \
            int idx = t + c * 128;                                              \
            int kk = idx >> 4, n4 = (idx & 15) * 4;                             \
            cp16(xd + (kk * GX_STR + n4) * 4,                                   \
                 &Xb[(size_t)((k0) + kk) * NPIX + n0 + n4]);                    \
        }                                                                       \
        cp_commit();                                                            \
    } while (0)

    STAGE_G(0, 0);
    const int nchunks = K / 32;
    for (int c0 = 0; c0 < nchunks; c0++) {
        cp_wait0();
        __syncthreads();
        if (c0 < nchunks - 1) STAGE_G((c0 + 1) * 32, (c0 + 1) & 1);

        const float* Wt = gsm + ((c0 & 1) ? OFF_W1 : OFF_W0);
        const float* Xs = gsm + ((c0 & 1) ? OFF_X1 : OFF_X0);
#pragma unroll
        for (int ks = 0; ks < 4; ks++) {
            u32 a[2][4];
#pragma unroll
            for (int g = 0; g < 2; g++) {
                int mr = 64 * g + 16 * w + r;
                a[g][0] = cvt_tf32(Wt[(mr    ) * GW_STR + ks * 8 + cq    ]);
                a[g][1] = cvt_tf32(Wt[(mr + 8) * GW_STR + ks * 8 + cq    ]);
                a[g][2] = cvt_tf32(Wt[(mr    ) * GW_STR + ks * 8 + cq + 4]);
                a[g][3] = cvt_tf32(Wt[(mr + 8) * GW_STR + ks * 8 + cq + 4]);
            }
#pragma unroll
            for (int nt = 0; nt < 8; nt++) {
                u32 b[2];
                b[0] = cvt_tf32(Xs[(ks * 8 + cq    ) * GX_STR + nt * 8 + r]);
                b[1] = cvt_tf32(Xs[(ks * 8 + cq + 4) * GX_STR + nt * 8 + r]);
                mma_tf32(acc[0][nt], a[0], b);
                mma_tf32(acc[1][nt], a[1], b);
            }
        }
    }

    // bh index for V half-write (QKV pass: one head per 128-row block)
    const int bh_v = bz * HEADS + (m0 >> 7);
    __half* vdst = g_v16 + (size_t)bh_v * HEAD_DIM * NPIX;

#pragma unroll
    for (int g = 0; g < 2; g++) {
        int row0 = m0 + 64 * g + 16 * w + r;
        int row1 = row0 + 8;
        float sc0 = gg[row0] * rsqrtf(vv[row0] + EPSBN);
        float bi0 = bb[row0] - mm[row0] * sc0;
        float sc1 = gg[row1] * rsqrtf(vv[row1] + EPSBN);
        float bi1 = bb[row1] - mm[row1] * sc1;
#pragma unroll
        for (int nt = 0; nt < 8; nt++) {
            int col = n0 + nt * 8 + 2 * cq;
            float o00 = acc[g][nt][0] * sc0 + bi0;
            float o01 = acc[g][nt][1] * sc0 + bi0;
            float o10 = acc[g][nt][2] * sc1 + bi1;
            float o11 = acc[g][nt][3] * sc1 + bi1;
            *(float2*)&Ob[(size_t)row0 * NPIX + col] = make_float2(o00, o01);
            *(float2*)&Ob[(size_t)row1 * NPIX + col] = make_float2(o10, o11);
            if (write_v && g == 1) {
                int dv0 = 16 * w + r;        // V channel for row0
                *(u32*)&vdst[(size_t)dv0 * NPIX + col]       = h2pack(o00, o01);
                *(u32*)&vdst[(size_t)(dv0 + 8) * NPIX + col] = h2pack(o10, o11);
            }
        }
    }
}

// ---------------------------------------------------------------------------
// Convert Q,K to half with transpose: g_qkv [ch][n] -> [n][d] per (b,h).
// ---------------------------------------------------------------------------
__global__ __launch_bounds__(128) void qk_cvt_kernel()
{
    const float QSCALE = 0.17677669529663687f * 1.4426950408889634f;
    __shared__ float ts[32][132];
    const int n0 = blockIdx.x * 128;
    const int bh = blockIdx.y;
    const int b  = bh >> 2;
    const int h  = bh & 3;
    const int qk = blockIdx.z;
    const int t  = threadIdx.x;

    const float* src = g_qkv + ((size_t)(b * HIDDEN + h * 128 + (qk ? 32 : 0))) * NPIX + n0;
    __half* dst = (qk ? g_k16 : g_q16) + ((size_t)bh * NPIX + n0) * KEY_DIM;
    const float scale = qk ? 1.0f : QSCALE;

#pragma unroll
    for (int d = 0; d < 32; d++) ts[d][t] = src[(size_t)d * NPIX + t];
    __syncthreads();

    u32 out[16];
#pragma unroll
    for (int d = 0; d < 16; d++)
        out[d] = h2pack(ts[2 * d][t] * scale, ts[2 * d + 1][t] * scale);
#pragma unroll
    for (int q4 = 0; q4 < 4; q4++)
        *(uint4*)&dst[(size_t)t * 32 + q4 * 8] =
            make_uint4(out[q4 * 4], out[q4 * 4 + 1], out[q4 * 4 + 2], out[q4 * 4 + 3]);
}

// ---------------------------------------------------------------------------
// Depthwise 3x3 conv + BN -> WRITES g_y (pre-init; attn adds on top).
// ---------------------------------------------------------------------------
__global__ __launch_bounds__(256) void pe_write_kernel(
    const float* __restrict__ pw, const float* __restrict__ pg,
    const float* __restrict__ pb, const float* __restrict__ pm,
    const float* __restrict__ pv)
{
    int idx = blockIdx.x * 256 + threadIdx.x;
    if (idx >= BATCH * DIMC * (NPIX / 4)) return;
    int n4 = (idx & 1023) * 4;
    int c  = (idx >> 10) & 255;
    int b  = idx >> 18;
    int yy = n4 >> 6, xx = n4 & 63;

    int vrow = (c >> 6) * 128 + 64 + (c & 63);
    const float* vimg = g_qkv + ((size_t)b * HIDDEN + vrow) * NPIX;

    float a0 = 0.f, a1 = 0.f, a2 = 0.f, a3 = 0.f;
#pragma unroll
    for (int ky = 0; ky < 3; ky++) {
        int y2 = yy + ky - 1;
        if (y2 < 0 || y2 >= HWDIM) continue;
        const float* row = vimg + y2 * HWDIM;
        float lm1 = (xx > 0)  ? row[xx - 1] : 0.f;
        float4 lc = *(const float4*)&row[xx];
        float l4  = (xx < 60) ? row[xx + 4] : 0.f;
        float w0 = pw[c * 9 + ky * 3 + 0];
        float w1 = pw[c * 9 + ky * 3 + 1];
        float w2 = pw[c * 9 + ky * 3 + 2];
        a0 += w0 * lm1  + w1 * lc.x + w2 * lc.y;
        a1 += w0 * lc.x + w1 * lc.y + w2 * lc.z;
        a2 += w0 * lc.y + w1 * lc.z + w2 * lc.w;
        a3 += w0 * lc.z + w1 * lc.w + w2 * l4;
    }
    float sc = pg[c] * rsqrtf(pv[c] + EPSBN);
    float bi = pb[c] - pm[c] * sc;
    *(float4*)&g_y[((size_t)b * DIMC + c) * NPIX + n4] =
        make_float4(a0 * sc + bi, a1 * sc + bi, a2 * sc + bi, a3 * sc + bi);
}

// ---------------------------------------------------------------------------
// Flash attention (round-8 proven config): fp16 m16n8k16, fp32 accum.
// 128 threads (4 warps); warp owns 32 queries (two 16-row tiles).
// Epilogue ADDS into g_y (pre-initialized with PE output).
// Grid = (NPIX/128, BATCH*HEADS).
// ---------------------------------------------------------------------------
#define RK 40
#define RV 72
#define KS_H (64 * RK)
#define VS_H (64 * RV)
#define AKS0 0
#define AKS1 KS_H
#define AVS0 (2 * KS_H)
#define AVS1 (2 * KS_H + VS_H)

__global__ __launch_bounds__(128) void attn_mma_kernel()
{
    __shared__ __align__(16) __half smh[2 * KS_H + 2 * VS_H];  // 28672 B
    const int bh   = blockIdx.y;
    const int i0   = blockIdx.x * 128;
    const int t    = threadIdx.x;
    const int w    = t >> 5;
    const int lane = t & 31;
    const int r    = lane >> 2;
    const int cq   = lane & 3;

    const __half* qb = g_q16 + (size_t)bh * NPIX * KEY_DIM;
    const __half* kb = g_k16 + (size_t)bh * NPIX * KEY_DIM;
    const __half* vb = g_v16 + (size_t)bh * HEAD_DIM * NPIX;
    const u32 smb = (u32)__cvta_generic_to_shared(smh);

    u32 qa[2][2][4];
#pragma unroll
    for (int rt = 0; rt < 2; rt++) {
        int row0 = i0 + 32 * w + 16 * rt + r;
#pragma unroll
        for (int ks = 0; ks < 2; ks++) {
            qa[rt][ks][0] = *(const u32*)&qb[(size_t)row0 * 32       + 16 * ks + 2 * cq];
            qa[rt][ks][1] = *(const u32*)&qb[(size_t)(row0 + 8) * 32 + 16 * ks + 2 * cq];
            qa[rt][ks][2] = *(const u32*)&qb[(size_t)row0 * 32       + 16 * ks + 8 + 2 * cq];
            qa[rt][ks][3] = *(const u32*)&qb[(size_t)(row0 + 8) * 32 + 16 * ks + 8 + 2 * cq];
        }
    }

    float o[2][8][4];
#pragma unroll
    for (int rt = 0; rt < 2; rt++)
#pragma unroll
        for (int nt = 0; nt < 8; nt++)
#pragma unroll
            for (int k = 0; k < 4; k++) o[rt][nt][k] = 0.f;
    float mx[2][2] = {{-1e30f, -1e30f}, {-1e30f, -1e30f}};
    float ll[2][2] = {{0.f, 0.f}, {0.f, 0.f}};

#define STAGE_A(kbase_idx, buf)                                                  \
    do {                                                                         \
        u32 kd = smb + ((buf) ? AKS1 : AKS0) * 2;                                \
        u32 vd = smb + ((buf) ? AVS1 : AVS0) * 2;                                \
        _Pragma("unroll")                                                        \
        for (int c = 0; c < 2; c++) {                                            \
            int idx = t + c * 128;                                               \
            int j = idx >> 2, seg = idx & 3;                                     \
            cp16(kd + (j * RK + seg * 8) * 2,                                    \
                 &kb[(size_t)((kbase_idx) + j) * 32 + seg * 8]);                 \
        }                                                                        \
        _Pragma("unroll")                                                        \
        for (int c = 0; c < 4; c++) {                                            \
            int idx = t + c * 128;                                               \
            int dv = idx >> 3, seg = idx & 7;                                    \
            cp16(vd + (dv * RV + seg * 8) * 2,                                   \
                 &vb[(size_t)dv * NPIX + (kbase_idx) + seg * 8]);                \
        }                                                                        \
        cp_commit();                                                             \
    } while (0)

    STAGE_A(0, 0);

    for (int tt = 0; tt < 64; tt++) {
        cp_wait0();
        __syncthreads();
        if (tt < 63) STAGE_A((tt + 1) * 64, (tt + 1) & 1);

        const __half* Ks = smh + ((tt & 1) ? AKS1 : AKS0);
        const __half* Vs = smh + ((tt & 1) ? AVS1 : AVS0);

        // ---- S = Q * K^T (K B-fragments shared across both row-tiles) ----
        float s[2][8][4];
#pragma unroll
        for (int rt = 0; rt < 2; rt++)
#pragma unroll
            for (int nt = 0; nt < 8; nt++)
#pragma unroll
                for (int k = 0; k < 4; k++) s[rt][nt][k] = 0.f;
#pragma unroll
        for (int ks = 0; ks < 2; ks++) {
#pragma unroll
            for (int nt = 0; nt < 8; nt++) {
                u32 b0 = *(const u32*)&Ks[(nt * 8 + r) * RK + 16 * ks + 2 * cq];
                u32 b1 = *(const u32*)&Ks[(nt * 8 + r) * RK + 16 * ks + 8 + 2 * cq];
                mma_f16(s[0][nt], qa[0][ks], b0, b1);
                mma_f16(s[1][nt], qa[1][ks], b0, b1);
            }
        }

        // ---- online softmax per row-tile ----
#pragma unroll
        for (int rt = 0; rt < 2; rt++) {
            float mx0 = mx[rt][0], mx1 = mx[rt][1];
#pragma unroll
            for (int nt = 0; nt < 8; nt++) {
                mx0 = fmaxf(mx0, fmaxf(s[rt][nt][0], s[rt][nt][1]));
                mx1 = fmaxf(mx1, fmaxf(s[rt][nt][2], s[rt][nt][3]));
            }
            mx0 = fmaxf(mx0, __shfl_xor_sync(0xffffffffu, mx0, 1));
            mx0 = fmaxf(mx0, __shfl_xor_sync(0xffffffffu, mx0, 2));
            mx1 = fmaxf(mx1, __shfl_xor_sync(0xffffffffu, mx1, 1));
            mx1 = fmaxf(mx1, __shfl_xor_sync(0xffffffffu, mx1, 2));
            float corr0 = ex2(mx[rt][0] - mx0);
            float corr1 = ex2(mx[rt][1] - mx1);
            mx[rt][0] = mx0; mx[rt][1] = mx1;

            float ps0 = 0.f, ps1 = 0.f;
#pragma unroll
            for (int nt = 0; nt < 8; nt++) {
                s[rt][nt][0] = ex2(s[rt][nt][0] - mx0);
                s[rt][nt][1] = ex2(s[rt][nt][1] - mx0);
                s[rt][nt][2] = ex2(s[rt][nt][2] - mx1);
                s[rt][nt][3] = ex2(s[rt][nt][3] - mx1);
                ps0 += s[rt][nt][0] + s[rt][nt][1];
                ps1 += s[rt][nt][2] + s[rt][nt][3];
            }
            ps0 += __shfl_xor_sync(0xffffffffu, ps0, 1);
            ps0 += __shfl_xor_sync(0xffffffffu, ps0, 2);
            ps1 += __shfl_xor_sync(0xffffffffu, ps1, 1);
            ps1 += __shfl_xor_sync(0xffffffffu, ps1, 2);
            ll[rt][0] = ll[rt][0] * corr0 + ps0;
            ll[rt][1] = ll[rt][1] * corr1 + ps1;

#pragma unroll
            for (int nt = 0; nt < 8; nt++) {
                o[rt][nt][0] *= corr0; o[rt][nt][1] *= corr0;
                o[rt][nt][2] *= corr1; o[rt][nt][3] *= corr1;
            }
        }

        // ---- O += P * V : A-fragments straight from S C-fragments ----
#pragma unroll
        for (int ks2 = 0; ks2 < 4; ks2++) {
            u32 pa[2][4];
#pragma unroll
            for (int rt = 0; rt < 2; rt++) {
                pa[rt][0] = h2pack(s[rt][2 * ks2    ][0], s[rt][2 * ks2    ][1]);
                pa[rt][1] = h2pack(s[rt][2 * ks2    ][2], s[rt][2 * ks2    ][3]);
                pa[rt][2] = h2pack(s[rt][2 * ks2 + 1][0], s[rt][2 * ks2 + 1][1]);
                pa[rt][3] = h2pack(s[rt][2 * ks2 + 1][2], s[rt][2 * ks2 + 1][3]);
            }
#pragma unroll
            for (int nt = 0; nt < 8; nt++) {
                u32 b0 = *(const u32*)&Vs[(nt * 8 + r) * RV + 16 * ks2 + 2 * cq];
                u32 b1 = *(const u32*)&Vs[(nt * 8 + r) * RV + 16 * ks2 + 8 + 2 * cq];
                mma_f16(o[0][nt], pa[0], b0, b1);
                mma_f16(o[1][nt], pa[1], b0, b1);
            }
        }
    }

    // ---- epilogue: normalize, ADD into g_y [dv][n] (pre-set to PE) ----
    const int b  = bh >> 2;
    const int h  = bh & 3;
    float* ybase = g_y + ((size_t)b * DIMC + h * 64) * NPIX;
#pragma unroll
    for (int rt = 0; rt < 2; rt++) {
        float inv0 = 1.f / ll[rt][0];
        float inv1 = 1.f / ll[rt][1];
        int row0 = i0 + 32 * w + 16 * rt + r;
        int row1 = row0 + 8;
#pragma unroll
        for (int nt = 0; nt < 8; nt++) {
            int dv0 = nt * 8 + 2 * cq;
            ybase[(size_t)(dv0    ) * NPIX + row0] += o[rt][nt][0] * inv0;
            ybase[(size_t)(dv0 + 1) * NPIX + row0] += o[rt][nt][1] * inv0;
            ybase[(size_t)(dv0    ) * NPIX + row1] += o[rt][nt][2] * inv1;
            ybase[(size_t)(dv0 + 1) * NPIX + row1] += o[rt][nt][3] * inv1;
        }
    }
}

// ---------------------------------------------------------------------------
extern "C" void kernel_launch(void* const* d_in, const int* in_sizes, int n_in,
                              void* d_out, int out_size)
{
    const float* x      = (const float*)d_in[0];
    const float* qkv_w  = (const float*)d_in[1];
    const float* qkv_g  = (const float*)d_in[2];
    const float* qkv_b  = (const float*)d_in[3];
    const float* qkv_m  = (const float*)d_in[4];
    const float* qkv_v  = (const float*)d_in[5];
    const float* proj_w = (const float*)d_in[6];
    const float* proj_g = (const float*)d_in[7];
    const float* proj_b = (const float*)d_in[8];
    const float* proj_m = (const float*)d_in[9];
    const float* proj_v = (const float*)d_in[10];
    const float* pe_w   = (const float*)d_in[11];
    const float* pe_g   = (const float*)d_in[12];
    const float* pe_b   = (const float*)d_in[13];
    const float* pe_m   = (const float*)d_in[14];
    const float* pe_v   = (const float*)d_in[15];
    float* out = (float*)d_out;

    static float* qkv_buf = nullptr;
    static float* y_buf   = nullptr;
    if (!qkv_buf) {
        cudaGetSymbolAddress((void**)&qkv_buf, g_qkv);
        cudaGetSymbolAddress((void**)&y_buf,   g_y);
        cudaFuncSetAttribute(gemm_mma_kernel,
                             cudaFuncAttributeMaxDynamicSharedMemorySize,
                             GEMM_SMEM_BYTES);
    }

    // 1) QKV 1x1 conv + BN (fused V -> half emit)
    {
        dim3 grid(NPIX / 64, HIDDEN / 128, BATCH);
        gemm_mma_kernel<<<grid, 128, GEMM_SMEM_BYTES>>>(
            x, qkv_w, qkv_g, qkv_b, qkv_m, qkv_v, qkv_buf, HIDDEN, DIMC, 1);
    }
    // 2) Convert Q/K (transpose) to half
    {
        dim3 gridqk(NPIX / 128, BATCH * HEADS, 2);
        qk_cvt_kernel<<<gridqk, 128>>>();
    }
    // 3) PE depthwise conv + BN -> writes g_y
    {
        int total = BATCH * DIMC * (NPIX / 4);
        pe_write_kernel<<<(total + 255) / 256, 256>>>(pe_w, pe_g, pe_b, pe_m, pe_v);
    }
    // 4) Attention (fp16 mma, round-8 config), adds into g_y
    {
        dim3 grid(NPIX / 128, BATCH * HEADS);
        attn_mma_kernel<<<grid, 128>>>();
    }
    // 5) proj 1x1 conv + BN -> out
    {
        dim3 grid(NPIX / 64, DIMC / 128, BATCH);
        gemm_mma_kernel<<<grid, 128, GEMM_SMEM_BYTES>>>(
            y_buf, proj_w, proj_g, proj_b, proj_m, proj_v, out, DIMC, DIMC, 0);
    }
}